// round 13
// baseline (speedup 1.0000x reference)
#include <cuda_runtime.h>
#include <cstdint>

// Problem constants (from reference)
#define DD   41
#define CCH  64
#define CHT  105          // DD + CCH
#define FH_  32
#define FW_  88
#define B_   4
#define NX0_ 200
#define NZ_  200
#define COLH (CHT * FH_)  // 3360 floats per (b,w) column
#define OUTN  (B_ * CCH * NZ_ * NX0_)   // 10,240,000 floats
#define FPAD 36           // sf pitch (conflict-free LDS/STS.128, 16B-aligned)
#define PBLK (105 * 3 * 2)  // 630 prep blocks (single wave => early trigger)

// Static scratch: x transposed to [b][w][ch][h] (4.73 MB)
__device__ float g_xT[(size_t)B_ * FW_ * COLH];

// ---------------------------------------------------------------------------
// Kernel 1 (PDL primary): transpose FIRST (2 b-tiles per block), then
// fence + trigger (dependent main may launch; transpose guaranteed visible
// via membar.gl + griddepcontrol.launch_dependents semantics), then the
// 41 MB zero-fill drains while main's front-end runs.
// grid (105, 3, 2) x 256 thr — 630 blocks, single wave.
// ---------------------------------------------------------------------------
__global__ __launch_bounds__(256) void lss_prep(const float* __restrict__ x,
                                                float* __restrict__ out) {
    __shared__ float tile[32][33];
    const int tx  = threadIdx.x & 31;
    const int ty  = threadIdx.x >> 5;
    const int tid = threadIdx.x;
    const int r0 = blockIdx.x * 32;   // row = ch*32+h
    const int c0 = blockIdx.y * 32;   // col = w

    // (a) transpose two b-slices: b = blockIdx.z and blockIdx.z + 2
#pragma unroll
    for (int bb = 0; bb < 2; bb++) {
        const int b = blockIdx.z + bb * 2;
        const float* xb = x + (size_t)b * COLH * FW_;
#pragma unroll
        for (int i = ty; i < 32; i += 8) {
            int r = r0 + i, c = c0 + tx;
            if (c < FW_) tile[i][tx] = xb[(size_t)r * FW_ + c];
        }
        __syncthreads();
        float* xt = g_xT + (size_t)b * FW_ * COLH;
#pragma unroll
        for (int i = ty; i < 32; i += 8) {
            int w = c0 + i, r = r0 + tx;
            if (w < FW_) xt[(size_t)w * COLH + r] = tile[tx][i];
        }
        __syncthreads();
    }

    // (b) publish transpose, allow dependent launch
    __threadfence();
    cudaTriggerProgrammaticLaunchCompletion();

    // (c) zero my slice of out (fire-and-forget STG.128; drains under main)
    {
        const int lin = (blockIdx.z * gridDim.y + blockIdx.y) * gridDim.x
                      + blockIdx.x;
        float4* o4 = (float4*)out;
        const int n4 = OUTN / 4;
        const float4 z4 = make_float4(0.f, 0.f, 0.f, 0.f);
        for (int i = lin * 256 + tid; i < n4; i += PBLK * 256) o4[i] = z4;
    }
}

// ---------------------------------------------------------------------------
// Kernel 2 (PDL secondary): main, R12 skeleton. One block per (w, b), 256 thr.
// Front-end (P1-P3) reads only g_xT (visible at launch); grid-dependency
// sync sits between P3 and P4 so atomics wait for the zero-fill drain.
// ---------------------------------------------------------------------------
__global__ __launch_bounds__(256) void lss_main(
    const float* __restrict__ intrins,
    const float* __restrict__ rots,
    const float* __restrict__ trans,
    float* __restrict__ out)
{
    __shared__ float wts[DD][FH_];                 // logits -> exp -> weights
    __shared__ __align__(16) float sf[CCH][FPAD];  // [c][h] feature stage
    __shared__ float pm[8][FH_];                   // per-group max
    __shared__ float ps[8][FH_];                   // per-group sum
    __shared__ float scale[8][FH_];                // exp(m_g - m)/s
    __shared__ int   binsp[DD];
    __shared__ int   flags[DD];        // 0 = no kept, 1 = uniform, 2 = mixed
    __shared__ int   binh[DD][FH_];
    __shared__ float iR[9], iK[9], tv[3];

    const int w    = blockIdx.x;
    const int b    = blockIdx.y;
    const int tid  = threadIdx.x;
    const int lane = tid & 31;
    const int wg   = tid >> 5;                 // 0..7
    const int c    = ((wg & 1) << 5) + lane;   // phase-4 channel
    const int dg   = wg >> 1;                  // phase-4 d-subgroup (0..3)

    const float* xt = g_xT + ((size_t)b * FW_ + w) * COLH;

    // P1a: logits 41x32 (contiguous) -> smem via float4
    {
        const float4* src = (const float4*)xt;
        float4* dst = (float4*)&wts[0][0];
        for (int i = tid; i < (DD * FH_) / 4; i += 256) dst[i] = src[i];
    }
    // P1b: features 64x32 -> sf[c][h]; global contiguous float4; STS.128
    {
        const float4* src = (const float4*)(xt + DD * FH_);
        for (int i = tid; i < (CCH * FH_) / 4; i += 256) {
            float4 v = src[i];
            int cc = i >> 3, h4 = (i & 7) << 2;
            *(float4*)&sf[cc][h4] = v;
        }
    }
    // P1c: PARALLEL 3x3 inversions (adjugate/det, correctly-rounded division
    // per entry — bit-identical to the serial version).
    if (tid < 18) {
        const int which = tid / 9;              // 0 = rots, 1 = intrins
        const int e     = tid % 9;
        const float* mm = which ? (intrins + b * 9) : (rots + b * 9);
        float a0 = mm[0], a1 = mm[1], a2 = mm[2];
        float a3 = mm[3], a4 = mm[4], a5 = mm[5];
        float a6 = mm[6], a7 = mm[7], a8 = mm[8];
        float c00 = a4 * a8 - a5 * a7;
        float c01 = a5 * a6 - a3 * a8;
        float c02 = a3 * a7 - a4 * a6;
        float det = a0 * c00 + a1 * c01 + a2 * c02;
        float num;
        switch (e) {
            case 0: num = c00; break;
            case 1: num = a2 * a7 - a1 * a8; break;
            case 2: num = a1 * a5 - a2 * a4; break;
            case 3: num = c01; break;
            case 4: num = a0 * a8 - a2 * a6; break;
            case 5: num = a2 * a3 - a0 * a5; break;
            case 6: num = c02; break;
            case 7: num = a1 * a6 - a0 * a7; break;
            default: num = a0 * a4 - a1 * a3; break;
        }
        float r = __fdiv_rn(num, det);
        if (which) iK[e] = r; else iR[e] = r;
    }
    if (tid < 3) tv[tid] = trans[b * 3 + tid];
    __syncthreads();

    // P2: single-pass group softmax. Thread (wg, lane): d = wg + 8k.
    {
        float m_t = -3.402823466e38f;
        for (int d = wg; d < DD; d += 8) m_t = fmaxf(m_t, wts[d][lane]);
        float s_t = 0.f;
        for (int d = wg; d < DD; d += 8) {
            float e = __expf(wts[d][lane] - m_t);
            wts[d][lane] = e;
            s_t += e;
        }
        pm[wg][lane] = m_t;
        ps[wg][lane] = s_t;
    }
    __syncthreads();
    if (tid < 32) {
        float m = pm[0][lane];
#pragma unroll
        for (int g = 1; g < 8; g++) m = fmaxf(m, pm[g][lane]);
        float s = 0.f;
#pragma unroll
        for (int g = 0; g < 8; g++) s += ps[g][lane] * __expf(pm[g][lane] - m);
        float rinv = __frcp_rn(s);
#pragma unroll
        for (int g = 0; g < 8; g++) scale[g][lane] = __expf(pm[g][lane] - m) * rinv;
    }
    __syncthreads();

    // P3: geometry. warp wg handles d = wg, wg+8, ...; lane = h.
    {
        const float xs = (float)w    * (703.0f / 87.0f);
        const float ys = (float)lane * (255.0f / 31.0f);
        const float r00 = iR[0], r01 = iR[1], r02 = iR[2];
        const float r10 = iR[3], r11 = iR[4], r12 = iR[5];
        const float r20 = iR[6], r21 = iR[7], r22 = iR[8];
        const float k00 = iK[0], k01 = iK[1], k02 = iK[2];
        const float k10 = iK[3], k11 = iK[4], k12 = iK[5];
        const float k20 = iK[6], k21 = iK[7], k22 = iK[8];
        const float t0 = tv[0], t1 = tv[1], t2 = tv[2];
        const float p0 = xs - t0, p1 = ys - t1;
        const float sc = scale[wg][lane];

        for (int d = wg; d < DD; d += 8) {
            float p2 = (4.0f + (float)d) - t2;
            float q0 = __fmaf_rn(r00, p0, __fmaf_rn(r01, p1, r02 * p2));
            float q1 = __fmaf_rn(r10, p0, __fmaf_rn(r11, p1, r12 * p2));
            float q2 = __fmaf_rn(r20, p0, __fmaf_rn(r21, p1, r22 * p2));
            float s0 = q0 * q2, s1 = q1 * q2, s2 = q2;
            float g0 = __fmaf_rn(k00, s0, __fmaf_rn(k01, s1, k02 * s2));
            float g1 = __fmaf_rn(k10, s0, __fmaf_rn(k11, s1, k12 * s2));
            float g2 = __fmaf_rn(k20, s0, __fmaf_rn(k21, s1, k22 * s2));
            // truncation toward zero matches astype(int32)
            int c0i = (int)((g0 + 50.0f) / 0.5f);
            int c1i = (int)((g1 + 10.0f) / 20.0f);
            int c2i = (int)(g2 / 0.25f);
            bool kept = (c0i >= 0) & (c0i < NX0_) & (c1i >= 0) & (c1i < 1) &
                        (c2i >= 0) & (c2i < NZ_);
            int sp = c2i * NX0_ + c0i;
            binh[d][lane] = sp;
            wts[d][lane] = kept ? wts[d][lane] * sc : 0.0f;

            unsigned km = __ballot_sync(0xffffffffu, kept);
            int fl = 0;
            if (km) {
                int src = __ffs(km) - 1;
                int lsp = __shfl_sync(0xffffffffu, sp, src);
                bool ok = (!kept) || (sp == lsp);
                fl = __all_sync(0xffffffffu, ok) ? 1 : 2;
                if (lane == 0) binsp[d] = lsp;
            }
            if (lane == 0) flags[d] = fl;
        }
    }
    __syncthreads();

    // Wait for the primary (zero-fill drain) before touching out.
    cudaGridDependencySynchronize();

    // P4: matvec + scatter. f regs via conflict-free LDS.128 from sf;
    // wts rows read as broadcast LDS.128 (128B-aligned rows).
    {
        float f[FH_];
        {
            const float4* sfc = (const float4*)&sf[c][0];
#pragma unroll
            for (int k = 0; k < 8; k++) {
                float4 v = sfc[k];
                f[4 * k + 0] = v.x; f[4 * k + 1] = v.y;
                f[4 * k + 2] = v.z; f[4 * k + 3] = v.w;
            }
        }

        float* ob = out + ((size_t)b * CCH + c) * (NZ_ * NX0_);
        for (int d = dg; d < DD; d += 4) {
            int fl = flags[d];
            if (fl == 0) continue;
            if (fl == 1) {
                const float4* wr = (const float4*)&wts[d][0];
                float a0 = 0.f, a1 = 0.f, a2 = 0.f, a3 = 0.f;
#pragma unroll
                for (int k = 0; k < 8; k++) {
                    float4 wv4 = wr[k];              // broadcast LDS.128
                    a0 = __fmaf_rn(wv4.x, f[4 * k + 0], a0);
                    a1 = __fmaf_rn(wv4.y, f[4 * k + 1], a1);
                    a2 = __fmaf_rn(wv4.z, f[4 * k + 2], a2);
                    a3 = __fmaf_rn(wv4.w, f[4 * k + 3], a3);
                }
                atomicAdd(ob + binsp[d], (a0 + a1) + (a2 + a3));
            } else {
                // generic fallback: per-h scatter
#pragma unroll
                for (int h = 0; h < FH_; h++) {
                    float wv = wts[d][h];
                    if (wv != 0.f) atomicAdd(ob + binh[d][h], wv * f[h]);
                }
            }
        }
    }
}

// ---------------------------------------------------------------------------
extern "C" void kernel_launch(void* const* d_in, const int* in_sizes, int n_in,
                              void* d_out, int out_size) {
    const float* x       = (const float*)d_in[0];
    const float* intrins = (const float*)d_in[1];
    const float* rots    = (const float*)d_in[2];
    const float* trans   = (const float*)d_in[3];
    float* out = (float*)d_out;

    // primary: transpose -> trigger -> zero-fill
    dim3 pgrid(COLH / 32, 3, 2);   // (105, 3, 2) = 630 blocks, single wave
    lss_prep<<<pgrid, 256>>>(x, out);

    // secondary: PDL — launches at primary's trigger, overlaps zero drain
    cudaLaunchConfig_t cfg = {};
    cfg.gridDim  = dim3(FW_, B_, 1);
    cfg.blockDim = dim3(256, 1, 1);
    cfg.dynamicSmemBytes = 0;
    cfg.stream = 0;
    cudaLaunchAttribute attrs[1];
    attrs[0].id = cudaLaunchAttributeProgrammaticStreamSerialization;
    attrs[0].val.programmaticStreamSerializationAllowed = 1;
    cfg.attrs = attrs;
    cfg.numAttrs = 1;
    cudaLaunchKernelEx(&cfg, lss_main, intrins, rots, trans, out);
}

// round 14
// speedup vs baseline: 1.0444x; 1.0444x over previous
#include <cuda_runtime.h>
#include <cstdint>

// Problem constants (from reference)
#define DD   41
#define CCH  64
#define CHT  105          // DD + CCH
#define FH_  32
#define FW_  88
#define B_   4
#define NX0_ 200
#define NZ_  200
#define COLH (CHT * FH_)  // 3360 floats per (b,w) column
#define FOFF (DD * FH_)   // 1312: feature slab offset within a column
#define OUTN  (B_ * CCH * NZ_ * NX0_)   // 10,240,000 floats

// Static scratch: per (b,w) column = [logits d*32+h (1312)] [features h*64+c (2048)]
__device__ float g_xT[(size_t)B_ * FW_ * COLH];   // 4.73 MB

// ---------------------------------------------------------------------------
// Kernel 1: fused (a) zero-fill of out and (b) layout transform.
// grid (105, 3, 4) x 256 thr:
//   blockIdx.x <  41 : logit tile  -> xT[b][w][d*32+h]        (old transpose)
//   blockIdx.x >= 41 : feature tile (h, cgroup) -> xT[b][w][1312 + h*64 + c]
// Both global sides coalesced.
// ---------------------------------------------------------------------------
__global__ __launch_bounds__(256) void lss_prep(const float* __restrict__ x,
                                                float* __restrict__ out) {
    __shared__ float tile[32][33];
    const int tx  = threadIdx.x & 31;
    const int ty  = threadIdx.x >> 5;
    const int tid = threadIdx.x;

    // (a) zero my slice of out (float4, grid-strided)
    {
        const int nblk = gridDim.x * gridDim.y * gridDim.z;          // 1260
        const int lin  = (blockIdx.z * gridDim.y + blockIdx.y) * gridDim.x
                       + blockIdx.x;
        float4* o4 = (float4*)out;
        const int n4 = OUTN / 4;
        const float4 z4 = make_float4(0.f, 0.f, 0.f, 0.f);
        for (int i = lin * 256 + tid; i < n4; i += nblk * 256) o4[i] = z4;
    }

    const int b  = blockIdx.z;
    const int c0 = blockIdx.y * 32;   // w-tile base
    const float* xb = x + (size_t)b * COLH * FW_;
    float* xt = g_xT + (size_t)b * FW_ * COLH;

    if (blockIdx.x < 41) {
        // (b1) logit tile: rows r = d*32+h, r0..r0+31 (all within 0..1311)
        const int r0 = blockIdx.x * 32;
#pragma unroll
        for (int i = ty; i < 32; i += 8) {
            int r = r0 + i, c = c0 + tx;
            if (c < FW_) tile[i][tx] = xb[(size_t)r * FW_ + c];
        }
        __syncthreads();
#pragma unroll
        for (int i = ty; i < 32; i += 8) {
            int w = c0 + i, r = r0 + tx;
            if (w < FW_) xt[(size_t)w * COLH + r] = tile[tx][i];
        }
    } else {
        // (b2) feature tile: fixed h and channel-group cg; gather 32 channels
        const int idx = blockIdx.x - 41;      // 0..63
        const int h   = idx >> 1;             // 0..31
        const int cg  = idx & 1;              // 0 or 1 (channels cg*32..+31)
        // load: tile[i][tx] = x[b][(41 + cg*32 + i)*32 + h][c0 + tx]
#pragma unroll
        for (int i = ty; i < 32; i += 8) {
            int row = (DD + cg * 32 + i) * FH_ + h;
            int c = c0 + tx;
            if (c < FW_) tile[i][tx] = xb[(size_t)row * FW_ + c];
        }
        __syncthreads();
        // store: xt[w][FOFF + h*64 + cg*32 + tx] = tile[tx][j], w = c0 + j
#pragma unroll
        for (int j = ty; j < 32; j += 8) {
            int w = c0 + j;
            if (w < FW_)
                xt[(size_t)w * COLH + FOFF + h * CCH + cg * 32 + tx] = tile[tx][j];
        }
    }
}

// ---------------------------------------------------------------------------
// Kernel 2: main. One block per (w, b), 256 thr, all 352 blocks one wave.
//  P1 : logits -> wts[41][32] smem; PARALLEL inv3. NO feature staging.
//  P2 : single-pass group softmax (2 barriers)
//  Pf : issue f[32] coalesced scalar LDGs (1 line/warp-load); latency
//       covered by P3's ALU
//  P3 : geometry + uniformity ballot; normalize via hoisted group scale
//  P4 : warp=(dg,chalf), lane=c; f in regs; wts rows broadcast LDS.128;
//       8 accumulators; ONE REDG per (d, channel).
// ---------------------------------------------------------------------------
__global__ __launch_bounds__(256, 3) void lss_main(
    const float* __restrict__ intrins,
    const float* __restrict__ rots,
    const float* __restrict__ trans,
    float* __restrict__ out)
{
    __shared__ float wts[DD][FH_];      // logits -> exp -> weights
    __shared__ float pm[8][FH_];        // per-group max
    __shared__ float ps[8][FH_];        // per-group sum
    __shared__ float scale[8][FH_];     // exp(m_g - m)/s
    __shared__ int   binsp[DD];
    __shared__ int   flags[DD];         // 0 = no kept, 1 = uniform, 2 = mixed
    __shared__ int   binh[DD][FH_];
    __shared__ float iR[9], iK[9], tv[3];

    const int w    = blockIdx.x;
    const int b    = blockIdx.y;
    const int tid  = threadIdx.x;
    const int lane = tid & 31;
    const int wg   = tid >> 5;                 // 0..7
    const int c    = ((wg & 1) << 5) + lane;   // phase-4 channel
    const int dg   = wg >> 1;                  // phase-4 d-subgroup (0..3)

    const float* xt = g_xT + ((size_t)b * FW_ + w) * COLH;

    // P1a: logits 41x32 (contiguous) -> smem via float4
    {
        const float4* src = (const float4*)xt;
        float4* dst = (float4*)&wts[0][0];
        for (int i = tid; i < FOFF / 4; i += 256) dst[i] = src[i];
    }
    // P1b: PARALLEL 3x3 inversions (adjugate/det, correctly-rounded division
    // per entry — bit-identical to the serial version).
    if (tid < 18) {
        const int which = tid / 9;              // 0 = rots, 1 = intrins
        const int e     = tid % 9;
        const float* mm = which ? (intrins + b * 9) : (rots + b * 9);
        float a0 = mm[0], a1 = mm[1], a2 = mm[2];
        float a3 = mm[3], a4 = mm[4], a5 = mm[5];
        float a6 = mm[6], a7 = mm[7], a8 = mm[8];
        float c00 = a4 * a8 - a5 * a7;
        float c01 = a5 * a6 - a3 * a8;
        float c02 = a3 * a7 - a4 * a6;
        float det = a0 * c00 + a1 * c01 + a2 * c02;
        float num;
        switch (e) {
            case 0: num = c00; break;
            case 1: num = a2 * a7 - a1 * a8; break;
            case 2: num = a1 * a5 - a2 * a4; break;
            case 3: num = c01; break;
            case 4: num = a0 * a8 - a2 * a6; break;
            case 5: num = a2 * a3 - a0 * a5; break;
            case 6: num = c02; break;
            case 7: num = a1 * a6 - a0 * a7; break;
            default: num = a0 * a4 - a1 * a3; break;
        }
        float r = __fdiv_rn(num, det);
        if (which) iK[e] = r; else iR[e] = r;
    }
    if (tid < 3) tv[tid] = trans[b * 3 + tid];
    __syncthreads();

    // P2: single-pass group softmax. Thread (wg, lane): d = wg + 8k.
    {
        float m_t = -3.402823466e38f;
        for (int d = wg; d < DD; d += 8) m_t = fmaxf(m_t, wts[d][lane]);
        float s_t = 0.f;
        for (int d = wg; d < DD; d += 8) {
            float e = __expf(wts[d][lane] - m_t);
            wts[d][lane] = e;
            s_t += e;
        }
        pm[wg][lane] = m_t;
        ps[wg][lane] = s_t;
    }
    __syncthreads();
    if (tid < 32) {
        float m = pm[0][lane];
#pragma unroll
        for (int g = 1; g < 8; g++) m = fmaxf(m, pm[g][lane]);
        float s = 0.f;
#pragma unroll
        for (int g = 0; g < 8; g++) s += ps[g][lane] * __expf(pm[g][lane] - m);
        float rinv = __frcp_rn(s);
#pragma unroll
        for (int g = 0; g < 8; g++) scale[g][lane] = __expf(pm[g][lane] - m) * rinv;
    }
    __syncthreads();

    // Pf: issue feature loads NOW (coalesced: warp lanes = consecutive c =>
    // each LDG.32 warp-op touches exactly one 128B line). P3's ALU covers
    // the L2 latency; consumed in P4.
    float f[FH_];
    {
        const float* xf = xt + FOFF + c;
#pragma unroll
        for (int h = 0; h < FH_; h++) f[h] = xf[h * CCH];
    }

    // P3: geometry. warp wg handles d = wg, wg+8, ...; lane = h.
    {
        const float xs = (float)w    * (703.0f / 87.0f);
        const float ys = (float)lane * (255.0f / 31.0f);
        const float r00 = iR[0], r01 = iR[1], r02 = iR[2];
        const float r10 = iR[3], r11 = iR[4], r12 = iR[5];
        const float r20 = iR[6], r21 = iR[7], r22 = iR[8];
        const float k00 = iK[0], k01 = iK[1], k02 = iK[2];
        const float k10 = iK[3], k11 = iK[4], k12 = iK[5];
        const float k20 = iK[6], k21 = iK[7], k22 = iK[8];
        const float t0 = tv[0], t1 = tv[1], t2 = tv[2];
        const float p0 = xs - t0, p1 = ys - t1;
        const float sc = scale[wg][lane];

        for (int d = wg; d < DD; d += 8) {
            float p2 = (4.0f + (float)d) - t2;
            float q0 = __fmaf_rn(r00, p0, __fmaf_rn(r01, p1, r02 * p2));
            float q1 = __fmaf_rn(r10, p0, __fmaf_rn(r11, p1, r12 * p2));
            float q2 = __fmaf_rn(r20, p0, __fmaf_rn(r21, p1, r22 * p2));
            float s0 = q0 * q2, s1 = q1 * q2, s2 = q2;
            float g0 = __fmaf_rn(k00, s0, __fmaf_rn(k01, s1, k02 * s2));
            float g1 = __fmaf_rn(k10, s0, __fmaf_rn(k11, s1, k12 * s2));
            float g2 = __fmaf_rn(k20, s0, __fmaf_rn(k21, s1, k22 * s2));
            // truncation toward zero matches astype(int32)
            int c0i = (int)((g0 + 50.0f) / 0.5f);
            int c1i = (int)((g1 + 10.0f) / 20.0f);
            int c2i = (int)(g2 / 0.25f);
            bool kept = (c0i >= 0) & (c0i < NX0_) & (c1i >= 0) & (c1i < 1) &
                        (c2i >= 0) & (c2i < NZ_);
            int sp = c2i * NX0_ + c0i;
            binh[d][lane] = sp;
            wts[d][lane] = kept ? wts[d][lane] * sc : 0.0f;

            unsigned km = __ballot_sync(0xffffffffu, kept);
            int fl = 0;
            if (km) {
                int src = __ffs(km) - 1;
                int lsp = __shfl_sync(0xffffffffu, sp, src);
                bool ok = (!kept) || (sp == lsp);
                fl = __all_sync(0xffffffffu, ok) ? 1 : 2;
                if (lane == 0) binsp[d] = lsp;
            }
            if (lane == 0) flags[d] = fl;
        }
    }
    __syncthreads();

    // P4: matvec + scatter. f in regs; wts rows broadcast LDS.128;
    // 8 independent accumulators.
    {
        float* ob = out + ((size_t)b * CCH + c) * (NZ_ * NX0_);
        for (int d = dg; d < DD; d += 4) {
            int fl = flags[d];
            if (fl == 0) continue;
            if (fl == 1) {
                const float4* wr = (const float4*)&wts[d][0];
                float a0 = 0.f, a1 = 0.f, a2 = 0.f, a3 = 0.f;
                float a4 = 0.f, a5 = 0.f, a6 = 0.f, a7 = 0.f;
#pragma unroll
                for (int k = 0; k < 8; k += 2) {
                    float4 u = wr[k];
                    float4 v = wr[k + 1];
                    a0 = __fmaf_rn(u.x, f[4 * k + 0], a0);
                    a1 = __fmaf_rn(u.y, f[4 * k + 1], a1);
                    a2 = __fmaf_rn(u.z, f[4 * k + 2], a2);
                    a3 = __fmaf_rn(u.w, f[4 * k + 3], a3);
                    a4 = __fmaf_rn(v.x, f[4 * k + 4], a4);
                    a5 = __fmaf_rn(v.y, f[4 * k + 5], a5);
                    a6 = __fmaf_rn(v.z, f[4 * k + 6], a6);
                    a7 = __fmaf_rn(v.w, f[4 * k + 7], a7);
                }
                atomicAdd(ob + binsp[d],
                          ((a0 + a1) + (a2 + a3)) + ((a4 + a5) + (a6 + a7)));
            } else {
                // generic fallback: per-h scatter
#pragma unroll
                for (int h = 0; h < FH_; h++) {
                    float wv = wts[d][h];
                    if (wv != 0.f) atomicAdd(ob + binh[d][h], wv * f[h]);
                }
            }
        }
    }
}

// ---------------------------------------------------------------------------
extern "C" void kernel_launch(void* const* d_in, const int* in_sizes, int n_in,
                              void* d_out, int out_size) {
    const float* x       = (const float*)d_in[0];
    const float* intrins = (const float*)d_in[1];
    const float* rots    = (const float*)d_in[2];
    const float* trans   = (const float*)d_in[3];
    float* out = (float*)d_out;

    // fused zero-fill + layout transform
    dim3 pgrid(105, 3, B_);   // 41 logit tiles + 64 feature tiles per (wtile,b)
    lss_prep<<<pgrid, 256>>>(x, out);

    dim3 mgrid(FW_, B_);
    lss_main<<<mgrid, 256>>>(intrins, rots, trans, out);
}